// round 17
// baseline (speedup 1.0000x reference)
#include <cuda_runtime.h>
#include <cuda_fp16.h>
#include <cstdint>

#define BB 8
#define NN 4096
#define CC 512
#define HH 8
#define HD 64
#define SCALE 0.125f
#define BHNHD (BB*HH*NN*HD)

#define TROWS 128
#define TBUF_H (TROWS * 64)
#define TBUF_BYTES (TBUF_H * 2)       // 16 KB
#define NSTAGE 3
#define SMEM_GEMM (NSTAGE * 2 * TBUF_BYTES)   // 96 KB per CTA

#define NCHUNK 8
#define CROWS (NN / NCHUNK)            // 512 rows per chunk

__device__ __half g_qkv[3ull * BHNHD];
__device__ __half g_xh[(size_t)BB * NN * CC];
__device__ __half g_w1h[3 * CC * CC];
__device__ __half g_w2h[CC * CC];
__device__ float  g_partq[64 * NCHUNK * 65];
__device__ float  g_partk[64 * NCHUNK * 65];

__device__ __forceinline__ uint32_t smem_u32(const void* p) {
    return (uint32_t)__cvta_generic_to_shared(p);
}
__device__ __forceinline__ void cp16(uint32_t dst, const void* src) {
    asm volatile("cp.async.cg.shared.global [%0], [%1], 16;"
        :: "r"(dst), "l"(src) : "memory");
}
#define CP_COMMIT() asm volatile("cp.async.commit_group;" ::: "memory")
#define CP_WAIT1()  asm volatile("cp.async.wait_group 1;" ::: "memory")

__device__ __forceinline__ void ldm_x4(uint32_t* r, uint32_t addr) {
    asm volatile("ldmatrix.sync.aligned.m8n8.x4.shared.b16 {%0,%1,%2,%3}, [%4];"
        : "=r"(r[0]), "=r"(r[1]), "=r"(r[2]), "=r"(r[3]) : "r"(addr));
}
__device__ __forceinline__ void mma_f16(float* c, const uint32_t* a, const uint32_t* b) {
    asm volatile(
        "mma.sync.aligned.m16n8k16.row.col.f32.f16.f16.f32 "
        "{%0,%1,%2,%3},{%4,%5,%6,%7},{%8,%9},{%0,%1,%2,%3};"
        : "+f"(c[0]), "+f"(c[1]), "+f"(c[2]), "+f"(c[3])
        : "r"(a[0]), "r"(a[1]), "r"(a[2]), "r"(a[3]), "r"(b[0]), "r"(b[1]));
}

// ---------------------------------------------------------------------------
// Single f32 -> f16 convert for x, w_qkv, w_proj
// ---------------------------------------------------------------------------
#define XQ  ((BB * NN * CC) / 4)
#define W1Q ((3 * CC * CC) / 4)
#define W2Q ((CC * CC) / 4)
__global__ void f2h_all(const float* __restrict__ x,
                        const float* __restrict__ w1,
                        const float* __restrict__ w2)
{
    const int total = XQ + W1Q + W2Q;
    for (int i = blockIdx.x * blockDim.x + threadIdx.x; i < total;
         i += gridDim.x * blockDim.x) {
        const float* src; __half* dst; int j;
        if (i < XQ)            { src = x;  dst = g_xh;  j = i; }
        else if (i < XQ + W1Q) { src = w1; dst = g_w1h; j = i - XQ; }
        else                   { src = w2; dst = g_w2h; j = i - XQ - W1Q; }
        float4 v = *(const float4*)(src + (size_t)j * 4);
        __half2 lo = __floats2half2_rn(v.x, v.y);
        __half2 hi = __floats2half2_rn(v.z, v.w);
        uint2 p; p.x = *(uint32_t*)&lo; p.y = *(uint32_t*)&hi;
        *(uint2*)(dst + (size_t)j * 4) = p;
    }
}

// ---------------------------------------------------------------------------
// Kernel 1: QKV GEMM. CTA 128x128 (256 thr, 2 CTAs/SM), k64 stages x 8,
// XOR-swizzled smem, 3-stage cp.async pipeline (verified).
// ---------------------------------------------------------------------------
__global__ void __launch_bounds__(256, 2) qkv_gemm_h(const __half* __restrict__ Xh,
                                                     const __half* __restrict__ Wh)
{
    extern __shared__ __half sm[];
    __half* As = sm;
    __half* Bs = sm + NSTAGE * TBUF_H;

    const int tid = threadIdx.x;
    const int m0 = blockIdx.y * 128;
    const int d0 = blockIdx.x * 128;

    int ar[4], ach[4]; uint32_t asmA[4], asmB[4];
    const __half* agp[4]; const __half* bgp[4];
#pragma unroll
    for (int i = 0; i < 4; i++) {
        int id = i * 256 + tid;
        ar[i] = id >> 3; ach[i] = id & 7;
        uint32_t off = ar[i] * 64 + ((ach[i] ^ (ar[i] & 7)) * 8);
        asmA[i] = smem_u32(As + off);
        asmB[i] = smem_u32(Bs + off);
        agp[i] = Xh + (size_t)(m0 + ar[i]) * CC + ach[i] * 8;
        bgp[i] = Wh + (size_t)(d0 + ar[i]) * CC + ach[i] * 8;
    }

    auto issue = [&](int s) {
        const int buf = s % NSTAGE;
#pragma unroll
        for (int i = 0; i < 4; i++) {
            cp16(asmA[i] + buf * TBUF_BYTES, agp[i] + s * 64);
            cp16(asmB[i] + buf * TBUF_BYTES, bgp[i] + s * 64);
        }
    };

    const int lane = tid & 31;
    const int warp = tid >> 5;
    const int wm = (warp & 1) * 64;
    const int wn = (warp >> 1) * 32;
    const int lr = lane >> 2;
    const int lc = lane & 3;

    uint32_t rowA[4], rowB[2];
#pragma unroll
    for (int mi = 0; mi < 4; mi++)
        rowA[mi] = smem_u32(As + (wm + mi * 16 + (lane & 15)) * 64);
#pragma unroll
    for (int nj = 0; nj < 2; nj++)
        rowB[nj] = smem_u32(Bs + (wn + nj * 16 + (lane & 7) + ((lane >> 4) * 8)) * 64);
    uint32_t aOff[4], bOff[4];
#pragma unroll
    for (int kk = 0; kk < 4; kk++) {
        aOff[kk] = (uint32_t)(((kk * 2 + (lane >> 4)) ^ (lane & 7)) << 4);
        bOff[kk] = (uint32_t)(((kk * 2 + ((lane >> 3) & 1)) ^ (lane & 7)) << 4);
    }

    float acc[4][4][4] = {};

    issue(0); CP_COMMIT();
    issue(1); CP_COMMIT();

#pragma unroll
    for (int s = 0; s < 8; ++s) {
        CP_WAIT1();
        __syncthreads();
        if (s + 2 < 8) issue(s + 2);
        CP_COMMIT();
        const uint32_t aB = (uint32_t)((s % NSTAGE) * TBUF_BYTES);
#pragma unroll
        for (int kk = 0; kk < 4; kk++) {
            uint32_t af[4][4], bf[2][4];
#pragma unroll
            for (int mi = 0; mi < 4; mi++) ldm_x4(af[mi], rowA[mi] + aB + aOff[kk]);
#pragma unroll
            for (int nj = 0; nj < 2; nj++) ldm_x4(bf[nj], rowB[nj] + aB + bOff[kk]);
#pragma unroll
            for (int mi = 0; mi < 4; ++mi)
#pragma unroll
                for (int ni = 0; ni < 4; ++ni)
                    mma_f16(acc[mi][ni], af[mi], &bf[ni >> 1][(ni & 1) * 2]);
        }
    }

#pragma unroll
    for (int mi = 0; mi < 4; ++mi) {
#pragma unroll
        for (int ni = 0; ni < 4; ++ni) {
            int d = d0 + wn + ni * 8 + 2 * lc;
            int t = d >> 9, h = (d >> 6) & 7, e = d & 63;
#pragma unroll
            for (int half = 0; half < 2; ++half) {
                int m = m0 + wm + mi * 16 + lr + half * 8;
                int b = m >> 12, n = m & 4095;
                __half2 hv = __floats2half2_rn(acc[mi][ni][half * 2 + 0],
                                               acc[mi][ni][half * 2 + 1]);
                *(__half2*)&g_qkv[(((size_t)t * BB + b) * HH + h) * ((size_t)NN * HD)
                                  + (size_t)n * HD + e] = hv;
            }
        }
    }
}

// ---------------------------------------------------------------------------
// Pool pass 1 (alpha over q): grid (64, NCHUNK), 512 threads, 8-row ILP.
// ---------------------------------------------------------------------------
__global__ void __launch_bounds__(512) pool_q(const float* __restrict__ wq)
{
    __shared__ float ws[HD];
    __shared__ float red[16][65];

    const int bh = blockIdx.x;
    const int h  = bh & 7;
    const int chunk = blockIdx.y;
    const int tid  = threadIdx.x;
    const int lane = tid & 31;
    const int warp = tid >> 5;

    const __half* src = g_qkv + (size_t)bh * NN * HD + (size_t)chunk * CROWS * HD;

    if (tid < HD) ws[tid] = wq[h * HD + tid] * SCALE;
    __syncthreads();

    const float w0 = ws[2 * lane], w1 = ws[2 * lane + 1];

    float a0 = 0.0f, a1 = 0.0f, se = 0.0f;
    for (int n = warp; n < CROWS; n += 128) {
        float2 r[8]; float v[8];
#pragma unroll
        for (int j = 0; j < 8; j++) {
            r[j] = __half22float2(*(const __half2*)(src + (size_t)(n + j * 16) * HD
                                                    + 2 * lane));
            v[j] = r[j].x * w0 + r[j].y * w1;
        }
#pragma unroll
        for (int o = 16; o; o >>= 1)
#pragma unroll
            for (int j = 0; j < 8; j++)
                v[j] += __shfl_xor_sync(0xffffffffu, v[j], o);
#pragma unroll
        for (int j = 0; j < 8; j++) {
            float e = __expf(v[j]);
            a0 += e * r[j].x;
            a1 += e * r[j].y;
            se += e;
        }
    }
    red[warp][2 * lane] = a0;
    red[warp][2 * lane + 1] = a1;
    if (lane == 0) red[warp][64] = se;
    __syncthreads();
    if (tid < 65) {
        float s = 0.0f;
#pragma unroll
        for (int w = 0; w < 16; w++) s += red[w][tid];
        g_partq[(bh * NCHUNK + chunk) * 65 + tid] = s;
    }
}

// ---------------------------------------------------------------------------
// Pool pass 2 (beta over k): derives gq inline from q-partials, 8-row ILP.
// ---------------------------------------------------------------------------
__global__ void __launch_bounds__(512) pool_k(const float* __restrict__ wk)
{
    __shared__ float ws[HD];
    __shared__ float red[16][65];

    const int bh = blockIdx.x;
    const int h  = bh & 7;
    const int chunk = blockIdx.y;
    const int tid  = threadIdx.x;
    const int lane = tid & 31;
    const int warp = tid >> 5;

    const __half* src = g_qkv + (size_t)BHNHD
                        + (size_t)bh * NN * HD + (size_t)chunk * CROWS * HD;

    if (tid < HD) {
        float val = 0.0f, sum = 0.0f;
#pragma unroll
        for (int c = 0; c < NCHUNK; c++) {
            val += g_partq[(bh * NCHUNK + c) * 65 + tid];
            sum += g_partq[(bh * NCHUNK + c) * 65 + 64];
        }
        ws[tid] = wk[h * HD + tid] * SCALE * (val / sum);
    }
    __syncthreads();

    const float w0 = ws[2 * lane], w1 = ws[2 * lane + 1];

    float a0 = 0.0f, a1 = 0.0f, se = 0.0f;
    for (int n = warp; n < CROWS; n += 128) {
        float2 r[8]; float v[8];
#pragma unroll
        for (int j = 0; j < 8; j++) {
            r[j] = __half22float2(*(const __half2*)(src + (size_t)(n + j * 16) * HD
                                                    + 2 * lane));
            v[j] = r[j].x * w0 + r[j].y * w1;
        }
#pragma unroll
        for (int o = 16; o; o >>= 1)
#pragma unroll
            for (int j = 0; j < 8; j++)
                v[j] += __shfl_xor_sync(0xffffffffu, v[j], o);
#pragma unroll
        for (int j = 0; j < 8; j++) {
            float e = __expf(v[j]);
            a0 += e * r[j].x;
            a1 += e * r[j].y;
            se += e;
        }
    }
    red[warp][2 * lane] = a0;
    red[warp][2 * lane + 1] = a1;
    if (lane == 0) red[warp][64] = se;
    __syncthreads();
    if (tid < 65) {
        float s = 0.0f;
#pragma unroll
        for (int w = 0; w < 16; w++) s += red[w][tid];
        g_partk[(bh * NCHUNK + chunk) * 65 + tid] = s;
    }
}

// ---------------------------------------------------------------------------
// Kernel 3: output GEMM — v x w_proj with gk applied on B fragments
// (fused wscale). gk derived in prologue from k-partials. Stage s = head s.
// Epilogue out = acc + b_proj + q(fp16).
// ---------------------------------------------------------------------------
__global__ void __launch_bounds__(256, 2) out_gemm_h(const float* __restrict__ bproj,
                                                     float* __restrict__ out)
{
    extern __shared__ __half sm[];
    __half* As = sm;
    __half* Bs = sm + NSTAGE * TBUF_H;
    __shared__ __half2 gkh[CC / 2];

    const int tid = threadIdx.x;
    const int m0 = blockIdx.y * 128;
    const int d0 = blockIdx.x * 128;
    const int bb = m0 >> 12;
    const int n0 = m0 & 4095;

    // derive gk[bb][c] from k-pool partials
    {
        int c0 = tid * 2;
        int h = c0 >> 6, e = c0 & 63;
        int bh = bb * 8 + h;
        float v0 = 0.0f, v1 = 0.0f, sum = 0.0f;
#pragma unroll
        for (int c = 0; c < NCHUNK; c++) {
            const float* p = &g_partk[(bh * NCHUNK + c) * 65];
            v0 += p[e];
            v1 += p[e + 1];
            sum += p[64];
        }
        float inv = 1.0f / sum;
        gkh[tid] = __floats2half2_rn(v0 * inv, v1 * inv);
    }

    const __half* vbase = g_qkv + 2ull * BHNHD;

    int ar[4], ach[4]; uint32_t asmA[4], asmB[4];
    const __half* bgp[4];
#pragma unroll
    for (int i = 0; i < 4; i++) {
        int id = i * 256 + tid;
        ar[i] = id >> 3; ach[i] = id & 7;
        uint32_t off = ar[i] * 64 + ((ach[i] ^ (ar[i] & 7)) * 8);
        asmA[i] = smem_u32(As + off);
        asmB[i] = smem_u32(Bs + off);
        bgp[i] = g_w2h + (size_t)(d0 + ar[i]) * CC + ach[i] * 8;
    }

    auto issue = [&](int s) {
        const int buf = s % NSTAGE;
#pragma unroll
        for (int i = 0; i < 4; i++) {
            cp16(asmA[i] + buf * TBUF_BYTES,
                 vbase + ((size_t)(bb * HH + s) * NN + n0 + ar[i]) * HD + ach[i] * 8);
            cp16(asmB[i] + buf * TBUF_BYTES, bgp[i] + s * 64);
        }
    };

    const int lane = tid & 31;
    const int warp = tid >> 5;
    const int wm = (warp & 1) * 64;
    const int wn = (warp >> 1) * 32;
    const int lr = lane >> 2;
    const int lc = lane & 3;

    uint32_t rowA[4], rowB[2];
#pragma unroll
    for (int mi = 0; mi < 4; mi++)
        rowA[mi] = smem_u32(As + (wm + mi * 16 + (lane & 15)) * 64);
#pragma unroll
    for (int nj = 0; nj < 2; nj++)
        rowB[nj] = smem_u32(Bs + (wn + nj * 16 + (lane & 7) + ((lane >> 4) * 8)) * 64);
    uint32_t aOff[4], bOff[4];
#pragma unroll
    for (int kk = 0; kk < 4; kk++) {
        aOff[kk] = (uint32_t)(((kk * 2 + (lane >> 4)) ^ (lane & 7)) << 4);
        bOff[kk] = (uint32_t)(((kk * 2 + ((lane >> 3) & 1)) ^ (lane & 7)) << 4);
    }

    float acc[4][4][4] = {};
    __syncthreads();   // gkh visible

    issue(0); CP_COMMIT();
    issue(1); CP_COMMIT();

#pragma unroll
    for (int s = 0; s < 8; ++s) {
        CP_WAIT1();
        __syncthreads();
        if (s + 2 < 8) issue(s + 2);
        CP_COMMIT();
        const uint32_t aB = (uint32_t)((s % NSTAGE) * TBUF_BYTES);
#pragma unroll
        for (int kk = 0; kk < 4; kk++) {
            const __half2 glo = gkh[s * 32 + kk * 8 + lc];
            const __half2 ghi = gkh[s * 32 + kk * 8 + 4 + lc];
            uint32_t af[4][4], bf[2][4];
#pragma unroll
            for (int mi = 0; mi < 4; mi++) ldm_x4(af[mi], rowA[mi] + aB + aOff[kk]);
#pragma unroll
            for (int nj = 0; nj < 2; nj++) {
                ldm_x4(bf[nj], rowB[nj] + aB + bOff[kk]);
                __half2* b2 = (__half2*)bf[nj];
                b2[0] = __hmul2(b2[0], glo);
                b2[1] = __hmul2(b2[1], ghi);
                b2[2] = __hmul2(b2[2], glo);
                b2[3] = __hmul2(b2[3], ghi);
            }
#pragma unroll
            for (int mi = 0; mi < 4; ++mi)
#pragma unroll
                for (int ni = 0; ni < 4; ++ni)
                    mma_f16(acc[mi][ni], af[mi], &bf[ni >> 1][(ni & 1) * 2]);
        }
    }

#pragma unroll
    for (int mi = 0; mi < 4; ++mi) {
#pragma unroll
        for (int ni = 0; ni < 4; ++ni) {
            int d = d0 + wn + ni * 8 + 2 * lc;
            int h = (d >> 6) & 7, e = d & 63;
            float bp0 = bproj[d], bp1 = bproj[d + 1];
#pragma unroll
            for (int half = 0; half < 2; ++half) {
                int m = m0 + wm + mi * 16 + lr + half * 8;
                int n = m & 4095;
                __half2 qh = *(const __half2*)&g_qkv[((size_t)(bb * HH + h) * NN + n)
                                                     * HD + e];
                float2 q = __half22float2(qh);
                float* op = &out[(size_t)m * CC + d];
                op[0] = acc[mi][ni][half * 2 + 0] + bp0 + q.x;
                op[1] = acc[mi][ni][half * 2 + 1] + bp1 + q.y;
            }
        }
    }
}

// ---------------------------------------------------------------------------
extern "C" void kernel_launch(void* const* d_in, const int* in_sizes, int n_in,
                              void* d_out, int out_size)
{
    const float* x      = (const float*)d_in[0];
    const float* w_qkv  = (const float*)d_in[1];
    const float* w_proj = (const float*)d_in[2];
    const float* b_proj = (const float*)d_in[3];
    const float* w_q    = (const float*)d_in[4];
    const float* w_k    = (const float*)d_in[5];
    float* out = (float*)d_out;

    static bool s_init = [] {
        cudaFuncSetAttribute(qkv_gemm_h,
                             cudaFuncAttributeMaxDynamicSharedMemorySize, SMEM_GEMM);
        cudaFuncSetAttribute(out_gemm_h,
                             cudaFuncAttributeMaxDynamicSharedMemorySize, SMEM_GEMM);
        return true;
    }();
    (void)s_init;

    __half* xh; cudaGetSymbolAddress((void**)&xh, g_xh);
    __half* w1h; cudaGetSymbolAddress((void**)&w1h, g_w1h);

    f2h_all<<<2048, 256>>>(x, w_qkv, w_proj);

    qkv_gemm_h<<<dim3(1536 / 128, 32768 / 128), 256, SMEM_GEMM>>>(xh, w1h);

    pool_q<<<dim3(64, NCHUNK), 512>>>(w_q);
    pool_k<<<dim3(64, NCHUNK), 512>>>(w_k);

    out_gemm_h<<<dim3(512 / 128, 32768 / 128), 256, SMEM_GEMM>>>(b_proj, out);
}